// round 14
// baseline (speedup 1.0000x reference)
#include <cuda_runtime.h>
#include <stdint.h>

// PatchMasker: out = concat(where(mask[t], 0, x_dist),
//                           where(mask[t], 0, x_tre),
//                           where(mask[t], 0, x_sea))
// x_* = (B=256, T=512, F=256) fp32, mask = (T=512,) int32.
//
// Converged HBM-streaming kernel at the B300 chip memory cap (~6.3 TB/s),
// minimal traffic (403 MB mandatory writes + kept-row-only reads ~ 587 MB).
// R13 -> R14: final policy probe — write-through stores (__stwt) instead of
// .cs, removing the write stream from L2 allocate/evict entirely. All other
// structure identical to the converged kernel: one tensor per blockIdx.y,
// 4 warp-coalesced float4 per thread, front-batched predicated .cs loads.

#define B_DIM 256
#define T_DIM 512
#define F_DIM 256

#define N4_PER ((long)B_DIM * T_DIM * F_DIM / 4)  // float4 per tensor = 2^23
#define ROW_SHIFT 6                               // 64 float4 per (b,t) row
#define T_MASK (T_DIM - 1)
#define BLK 256
#define F4_PER_THREAD 4
#define F4_PER_BLOCK (F4_PER_THREAD * BLK)        // 1024

__global__ void __launch_bounds__(BLK, 8)
patch_masker_kernel(const float4* __restrict__ xd,
                    const float4* __restrict__ xt,
                    const float4* __restrict__ xs,
                    const int* __restrict__ mask,
                    float4* __restrict__ out)
{
    // One tensor per blockIdx.y: exactly 1 read + 1 write stream per block.
    const float4* __restrict__ src =
        (blockIdx.y == 0) ? xd : (blockIdx.y == 1) ? xt : xs;
    float4* __restrict__ dst = out + (long)blockIdx.y * N4_PER;

    long base = (long)blockIdx.x * F4_PER_BLOCK + threadIdx.x;

    const float4 z = make_float4(0.f, 0.f, 0.f, 0.f);
    float4 v[F4_PER_THREAD];
    bool  k[F4_PER_THREAD];
    long  idx[F4_PER_THREAD];

#pragma unroll
    for (int j = 0; j < F4_PER_THREAD; j++) {
        idx[j] = base + (long)j * BLK;               // warp-contiguous
        int t = (int)((idx[j] >> ROW_SHIFT) & T_MASK);
        k[j] = (mask[t] == 0);                       // 2 KB table, L1-resident
        v[j] = z;
    }

    // Front-batched independent predicated loads (up to 4 LDG.128 in flight);
    // masked rows generate zero read traffic.
#pragma unroll
    for (int j = 0; j < F4_PER_THREAD; j++) {
        if (k[j]) v[j] = __ldcs(&src[idx[j]]);
    }

    // Write-through stores: no L2 allocation for the write stream.
#pragma unroll
    for (int j = 0; j < F4_PER_THREAD; j++) {
        __stwt(&dst[idx[j]], v[j]);
    }
}

extern "C" void kernel_launch(void* const* d_in, const int* in_sizes, int n_in,
                              void* d_out, int out_size)
{
    const float4* xd = (const float4*)d_in[0];
    const float4* xt = (const float4*)d_in[1];
    const float4* xs = (const float4*)d_in[2];
    const int* mask  = (const int*)d_in[3];
    float4* out = (float4*)d_out;

    dim3 grid((unsigned)(N4_PER / F4_PER_BLOCK), 3);  // (8192, 3), exact
    patch_masker_kernel<<<grid, BLK>>>(xd, xt, xs, mask, out);
}

// round 15
// speedup vs baseline: 1.0052x; 1.0052x over previous
#include <cuda_runtime.h>
#include <stdint.h>

// PatchMasker: out = concat(where(mask[t], 0, x_dist),
//                           where(mask[t], 0, x_tre),
//                           where(mask[t], 0, x_sea))
// x_* = (B=256, T=512, F=256) fp32, mask = (T=512,) int32.
//
// FINAL (converged at the roofline): pure HBM-streaming kernel pinned at the
// B300 chip-level memory throughput cap (6.24-6.38 TB/s across runs; spread
// is the HW's own run-to-run variation band). Traffic is information-
// theoretically minimal: all 403 MB of output written (d_out is poisoned,
// zeros must be materialized), input reads predicated off for masked rows
// (~40% of T), ~587 MB total -> ~93 us at the cap.
//
// Fully-populated optimization matrix (each cell ncu-measured):
//   coalescing: strided pairs .... -19% (32B-sector waste)
//   scheduling: persistent CTAs .. -21% (occupancy/L1tex-queue underfill)
//   MLP 3/4/6 per thread ......... identical (+-0.3%)
//   128-bit vs 256-bit accesses .. identical (+-1%)
//   stream layouts (6 vs 2/blk) .. identical
//   store policy .cs vs .wt ...... identical
//
// Structure: one tensor per blockIdx.y (1 read + 1 write stream per block),
// 4 warp-coalesced float4 per thread, front-batched predicated loads,
// streaming (.cs) cache policy.

#define B_DIM 256
#define T_DIM 512
#define F_DIM 256

#define N4_PER ((long)B_DIM * T_DIM * F_DIM / 4)  // float4 per tensor = 2^23
#define ROW_SHIFT 6                               // 64 float4 per (b,t) row
#define T_MASK (T_DIM - 1)
#define BLK 256
#define F4_PER_THREAD 4
#define F4_PER_BLOCK (F4_PER_THREAD * BLK)        // 1024

__global__ void __launch_bounds__(BLK, 8)
patch_masker_kernel(const float4* __restrict__ xd,
                    const float4* __restrict__ xt,
                    const float4* __restrict__ xs,
                    const int* __restrict__ mask,
                    float4* __restrict__ out)
{
    // One tensor per blockIdx.y: exactly 1 read + 1 write stream per block.
    const float4* __restrict__ src =
        (blockIdx.y == 0) ? xd : (blockIdx.y == 1) ? xt : xs;
    float4* __restrict__ dst = out + (long)blockIdx.y * N4_PER;

    long base = (long)blockIdx.x * F4_PER_BLOCK + threadIdx.x;

    const float4 z = make_float4(0.f, 0.f, 0.f, 0.f);
    float4 v[F4_PER_THREAD];
    bool  k[F4_PER_THREAD];
    long  idx[F4_PER_THREAD];

#pragma unroll
    for (int j = 0; j < F4_PER_THREAD; j++) {
        idx[j] = base + (long)j * BLK;               // warp-contiguous
        int t = (int)((idx[j] >> ROW_SHIFT) & T_MASK);
        k[j] = (mask[t] == 0);                       // 2 KB table, L1-resident
        v[j] = z;
    }

    // Front-batched independent predicated loads (up to 4 LDG.128 in flight);
    // masked rows generate zero read traffic.
#pragma unroll
    for (int j = 0; j < F4_PER_THREAD; j++) {
        if (k[j]) v[j] = __ldcs(&src[idx[j]]);
    }

#pragma unroll
    for (int j = 0; j < F4_PER_THREAD; j++) {
        __stcs(&dst[idx[j]], v[j]);
    }
}

extern "C" void kernel_launch(void* const* d_in, const int* in_sizes, int n_in,
                              void* d_out, int out_size)
{
    const float4* xd = (const float4*)d_in[0];
    const float4* xt = (const float4*)d_in[1];
    const float4* xs = (const float4*)d_in[2];
    const int* mask  = (const int*)d_in[3];
    float4* out = (float4*)d_out;

    dim3 grid((unsigned)(N4_PER / F4_PER_BLOCK), 3);  // (8192, 3), exact
    patch_masker_kernel<<<grid, BLK>>>(xd, xt, xs, mask, out);
}